// round 9
// baseline (speedup 1.0000x reference)
#include <cuda_runtime.h>
#include <cuda_bf16.h>
#include <math.h>

// ---------------- problem constants ----------------
#define BATCH   256
#define IMG     224
#define CCH     3
#define NP      16
#define PS      14
#define INPUT_D 588           // 3*14*14
#define HIDDEN  128
#define NHEADS  2
#define DHEAD   64
#define NBLOCKS 2
#define MLP     512
#define OUTD    1000
#define SEQ     257           // 16*16 + 1
#define MTOK    (BATCH*SEQ)   // 65792 = 514*128
#define MPATCH  (BATCH*NP*NP) // 65536

// ---------------- scratch (device globals; no allocation allowed) ----------------
__device__ float g_out[MTOK*HIDDEN];        // residual stream
__device__ float g_x  [MTOK*HIDDEN];        // LN output
__device__ float g_qkv[MTOK*3*HIDDEN];      // fused q|k|v
__device__ float g_h1 [MTOK*MLP];           // MLP hidden
__device__ float g_mapWT[INPUT_D*HIDDEN];
__device__ float g_qkvW[NBLOCKS*HIDDEN*3*HIDDEN];   // [blk][d][3*128] block-diagonal combined
__device__ float g_qkvB[NBLOCKS*3*HIDDEN];
__device__ float g_w1T[NBLOCKS*HIDDEN*MLP];
__device__ float g_w2T[NBLOCKS*MLP*HIDDEN];
__device__ float g_headWT[HIDDEN*OUTD];
__device__ float g_pos[SEQ*HIDDEN];

// ---------------- prep: weight transposes, combined QKV, positional table ----------------
#define S0 (INPUT_D*HIDDEN)            // mapWT       75264
#define S1 (NBLOCKS*HIDDEN*3*HIDDEN)   // qkvW        98304
#define S2 (NBLOCKS*3*HIDDEN)          // qkvB          768
#define S3 (NBLOCKS*HIDDEN*MLP)        // w1T        131072
#define S4 (NBLOCKS*MLP*HIDDEN)        // w2T        131072
#define S5 (HIDDEN*OUTD)               // headWT     128000
#define S6 (SEQ*HIDDEN)                // pos         32896
#define PREP_TOTAL (S0+S1+S2+S3+S4+S5+S6)

__global__ void prep_kernel(const float* __restrict__ mapW,
                            const float* __restrict__ qW, const float* __restrict__ qb,
                            const float* __restrict__ kW, const float* __restrict__ kb,
                            const float* __restrict__ vW, const float* __restrict__ vb,
                            const float* __restrict__ w1, const float* __restrict__ w2,
                            const float* __restrict__ headW)
{
    for (int idx = blockIdx.x*blockDim.x + threadIdx.x; idx < PREP_TOTAL;
         idx += gridDim.x*blockDim.x) {
        int t = idx;
        if (t < S0) {                       // mapWT[d][e] = mapW[e][d]
            int d = t / HIDDEN, e = t % HIDDEN;
            g_mapWT[t] = mapW[e*INPUT_D + d];
            continue;
        }
        t -= S0;
        if (t < S1) {                       // combined block-diagonal QKV weight
            int blk = t / (HIDDEN*3*HIDDEN);
            int rr  = t % (HIDDEN*3*HIDDEN);
            int dfull = rr / (3*HIDDEN);
            int col   = rr % (3*HIDDEN);
            int sect  = col / HIDDEN;       // 0=q 1=k 2=v
            int ef    = col % HIDDEN;
            int h = ef >> 6, e = ef & 63, d = dfull & 63;
            float val = 0.f;
            if ((dfull >> 6) == h) {
                const float* W = (sect==0)? qW : (sect==1)? kW : vW;
                val = W[(((blk*NHEADS)+h)*DHEAD + e)*DHEAD + d];
            }
            g_qkvW[t] = val;
            continue;
        }
        t -= S1;
        if (t < S2) {                       // combined bias
            int blk = t / (3*HIDDEN);
            int col = t % (3*HIDDEN);
            int sect = col / HIDDEN;
            int ef   = col % HIDDEN;
            int h = ef >> 6, e = ef & 63;
            const float* B = (sect==0)? qb : (sect==1)? kb : vb;
            g_qkvB[t] = B[((blk*NHEADS)+h)*DHEAD + e];
            continue;
        }
        t -= S2;
        if (t < S3) {                       // w1T[blk][k][n] = w1[blk][n][k]
            int blk = t / (HIDDEN*MLP);
            int rr  = t % (HIDDEN*MLP);
            int k = rr / MLP, n = rr % MLP;
            g_w1T[t] = w1[(blk*MLP + n)*HIDDEN + k];
            continue;
        }
        t -= S3;
        if (t < S4) {                       // w2T[blk][k][n] = w2[blk][n][k]
            int blk = t / (MLP*HIDDEN);
            int rr  = t % (MLP*HIDDEN);
            int k = rr / HIDDEN, n = rr % HIDDEN;
            g_w2T[t] = w2[(blk*HIDDEN + n)*MLP + k];
            continue;
        }
        t -= S4;
        if (t < S5) {                       // headWT[k][n] = headW[n][k]
            int k = t / OUTD, n = t % OUTD;
            g_headWT[t] = headW[n*HIDDEN + k];
            continue;
        }
        t -= S5;
        {                                   // positional embedding (fp64, matches numpy)
            int i = t / HIDDEN, j = t % HIDDEN;
            double ex   = (double)(j - (j & 1)) / (double)HIDDEN;
            double freq = pow(10000.0, ex);
            double arg  = (double)i / freq;
            g_pos[t] = (j & 1) ? (float)cos(arg) : (float)sin(arg);
        }
    }
}

// ---------------- cls token rows: out[b][0] = cls + pos[0] ----------------
__global__ void cls_pos_kernel(const float* __restrict__ cls)
{
    int idx = blockIdx.x*blockDim.x + threadIdx.x;     // 256*128
    if (idx >= BATCH*HIDDEN) return;
    int b = idx >> 7, j = idx & 127;
    g_out[(size_t)b*SEQ*HIDDEN + j] = cls[j] + g_pos[j];
}

// ---------------- patch-embed GEMM (LUT gather A) + pos add, 64x64 tiles ----------------
__global__ void __launch_bounds__(256)
patch_embed_kernel(const float* __restrict__ images,
                   const float* __restrict__ mapb)
{
    __shared__ __align__(16) float As[16][68];   // padded: avoids 16-way write conflicts
    __shared__ __align__(16) float Bs[16][64];
    __shared__ int coltab[INPUT_D];              // k -> image offset within a patch row-base
    __shared__ int rowbase[64];                  // tile row -> image base offset
    const int K = INPUT_D, N = HIDDEN;
    int tid  = threadIdx.x;
    int row0 = blockIdx.y * 64;
    int col0 = blockIdx.x * 64;
    int tr = tid >> 4, tc = tid & 15;

    // fill LUTs once per block
    for (int k = tid; k < INPUT_D; k += 256) {
        int cc = k / 196; int rem = k - cc*196;
        int u  = rem / 14; int v14 = rem - u*14;
        coltab[k] = cc*IMG*IMG + u*IMG + v14;
    }
    if (tid < 64) {
        int gr = row0 + tid;
        int b  = gr >> 8, patch = gr & 255;
        int py = patch >> 4, px = patch & 15;
        rowbase[tid] = b*CCH*IMG*IMG + (py*PS)*IMG + px*PS;
    }
    __syncthreads();

    float acc[4][4];
    #pragma unroll
    for (int i=0;i<4;i++)
        #pragma unroll
        for (int j=0;j<4;j++) acc[i][j]=0.f;

    for (int k0 = 0; k0 < K; k0 += 16) {
        #pragma unroll
        for (int i=0;i<4;i++) {
            int li = tid + i*256;
            int r = li >> 4, c = li & 15;
            int gk = k0 + c;
            float v = 0.f;
            if (gk < K)
                v = images[(size_t)(rowbase[r] + coltab[gk])];
            As[c][r] = v;
        }
        #pragma unroll
        for (int i=0;i<4;i++) {
            int li = tid + i*256;
            int r = li >> 6, c = li & 63;
            int gk = k0 + r;
            Bs[r][c] = (gk < K) ? g_mapWT[(size_t)gk*N + col0 + c] : 0.f;
        }
        __syncthreads();
        #pragma unroll
        for (int kk=0;kk<16;kk++){
            float4 av = *reinterpret_cast<const float4*>(&As[kk][tr*4]);
            float4 bv = *reinterpret_cast<const float4*>(&Bs[kk][tc*4]);
            acc[0][0]+=av.x*bv.x; acc[0][1]+=av.x*bv.y; acc[0][2]+=av.x*bv.z; acc[0][3]+=av.x*bv.w;
            acc[1][0]+=av.y*bv.x; acc[1][1]+=av.y*bv.y; acc[1][2]+=av.y*bv.z; acc[1][3]+=av.y*bv.w;
            acc[2][0]+=av.z*bv.x; acc[2][1]+=av.z*bv.y; acc[2][2]+=av.z*bv.z; acc[2][3]+=av.z*bv.w;
            acc[3][0]+=av.w*bv.x; acc[3][1]+=av.w*bv.y; acc[3][2]+=av.w*bv.z; acc[3][3]+=av.w*bv.w;
        }
        __syncthreads();
    }
    #pragma unroll
    for (int i=0;i<4;i++){
        int gr = row0 + tr*4 + i;
        int b  = gr >> 8, patch = gr & 255;
        size_t drow = (size_t)b*SEQ + 1 + patch;
        #pragma unroll
        for (int j=0;j<4;j++){
            int cc = col0 + tc*4 + j;
            g_out[drow*HIDDEN + cc] = acc[i][j] + mapb[cc] + g_pos[(1+patch)*HIDDEN + cc];
        }
    }
}

// ---------------- 128x128-tile SGEMM, double-buffered smem ----------------
// 256 threads, 8x8 microtile. M%128==0, N%128==0, K%16==0.
#define GF_GELU 1
#define GF_ACC  2
__global__ void __launch_bounds__(256)
sgemm128_kernel(const float* __restrict__ A, const float* __restrict__ B,
                const float* __restrict__ bias, float* __restrict__ C,
                int N, int K, int flags)
{
    __shared__ __align__(16) float As[2][16][136];
    __shared__ __align__(16) float Bs[2][16][128];
    int tid  = threadIdx.x;
    int row0 = blockIdx.y * 128;
    int col0 = blockIdx.x * 128;
    int tr = tid >> 4, tc = tid & 15;            // 16x16 thread grid

    // per-thread load coordinates (constant over k)
    int ra  = (tid*2)   >> 2, kqa = (tid*2)   & 3;    // A elem 0
    int ra2 = (tid*2+1) >> 2, kqa2= (tid*2+1) & 3;    // A elem 1
    int rb  = (tid*2)   >> 5, cb  = (tid*2)   & 31;   // B elem 0
    int rb2 = (tid*2+1) >> 5, cb2 = (tid*2+1) & 31;   // B elem 1

    float acc[2][2][4][4];
    #pragma unroll
    for (int rh=0;rh<2;rh++)
        #pragma unroll
        for (int ch=0;ch<2;ch++)
            #pragma unroll
            for (int i=0;i<4;i++)
                #pragma unroll
                for (int j=0;j<4;j++) acc[rh][ch][i][j]=0.f;

    const int ntiles = K >> 4;

    // preload tile 0 into buffer 0
    {
        float4 a0 = *reinterpret_cast<const float4*>(&A[(size_t)(row0+ra )*K + kqa *4]);
        float4 a1 = *reinterpret_cast<const float4*>(&A[(size_t)(row0+ra2)*K + kqa2*4]);
        float4 b0 = *reinterpret_cast<const float4*>(&B[(size_t)(rb )*N + col0 + cb *4]);
        float4 b1 = *reinterpret_cast<const float4*>(&B[(size_t)(rb2)*N + col0 + cb2*4]);
        As[0][kqa *4+0][ra ]=a0.x; As[0][kqa *4+1][ra ]=a0.y; As[0][kqa *4+2][ra ]=a0.z; As[0][kqa *4+3][ra ]=a0.w;
        As[0][kqa2*4+0][ra2]=a1.x; As[0][kqa2*4+1][ra2]=a1.y; As[0][kqa2*4+2][ra2]=a1.z; As[0][kqa2*4+3][ra2]=a1.w;
        *reinterpret_cast<float4*>(&Bs[0][rb ][cb *4]) = b0;
        *reinterpret_cast<float4*>(&Bs[0][rb2][cb2*4]) = b1;
    }
    __syncthreads();

    int buf = 0;
    for (int t = 0; t < ntiles; t++) {
        float4 pa0, pa1, pb0, pb1;
        bool more = (t+1 < ntiles);
        if (more) {                           // prefetch next tile into registers
            int k0 = (t+1) << 4;
            pa0 = *reinterpret_cast<const float4*>(&A[(size_t)(row0+ra )*K + k0 + kqa *4]);
            pa1 = *reinterpret_cast<const float4*>(&A[(size_t)(row0+ra2)*K + k0 + kqa2*4]);
            pb0 = *reinterpret_cast<const float4*>(&B[(size_t)(k0+rb )*N + col0 + cb *4]);
            pb1 = *reinterpret_cast<const float4*>(&B[(size_t)(k0+rb2)*N + col0 + cb2*4]);
        }
        // compute current buffer
        #pragma unroll
        for (int kk=0;kk<16;kk++){
            float4 a0 = *reinterpret_cast<const float4*>(&As[buf][kk][tr*4]);
            float4 a1 = *reinterpret_cast<const float4*>(&As[buf][kk][tr*4+64]);
            float4 b0 = *reinterpret_cast<const float4*>(&Bs[buf][kk][tc*4]);
            float4 b1 = *reinterpret_cast<const float4*>(&Bs[buf][kk][tc*4+64]);
            float ar[8] = {a0.x,a0.y,a0.z,a0.w, a1.x,a1.y,a1.z,a1.w};
            float br[8] = {b0.x,b0.y,b0.z,b0.w, b1.x,b1.y,b1.z,b1.w};
            #pragma unroll
            for (int rh=0;rh<2;rh++)
                #pragma unroll
                for (int i=0;i<4;i++)
                    #pragma unroll
                    for (int ch=0;ch<2;ch++)
                        #pragma unroll
                        for (int j=0;j<4;j++)
                            acc[rh][ch][i][j] += ar[rh*4+i]*br[ch*4+j];
        }
        if (more) {                           // stage next tile into alternate buffer
            int nb = buf ^ 1;
            As[nb][kqa *4+0][ra ]=pa0.x; As[nb][kqa *4+1][ra ]=pa0.y; As[nb][kqa *4+2][ra ]=pa0.z; As[nb][kqa *4+3][ra ]=pa0.w;
            As[nb][kqa2*4+0][ra2]=pa1.x; As[nb][kqa2*4+1][ra2]=pa1.y; As[nb][kqa2*4+2][ra2]=pa1.z; As[nb][kqa2*4+3][ra2]=pa1.w;
            *reinterpret_cast<float4*>(&Bs[nb][rb ][cb *4]) = pb0;
            *reinterpret_cast<float4*>(&Bs[nb][rb2][cb2*4]) = pb1;
            __syncthreads();
            buf = nb;
        }
    }

    #pragma unroll
    for (int rh=0;rh<2;rh++){
        #pragma unroll
        for (int i=0;i<4;i++){
            size_t gr = row0 + rh*64 + tr*4 + i;
            #pragma unroll
            for (int ch=0;ch<2;ch++){
                #pragma unroll
                for (int j=0;j<4;j++){
                    int cc = col0 + ch*64 + tc*4 + j;
                    float v = acc[rh][ch][i][j] + bias[cc];
                    if (flags & GF_GELU)
                        v = 0.5f * v * (1.0f + erff(v * 0.70710678118654752f));
                    size_t idx = gr*N + cc;
                    if (flags & GF_ACC) C[idx] += v; else C[idx] = v;
                }
            }
        }
    }
}

// ---------------- layernorm: one warp per row, shuffle-only reductions ----------------
__global__ void __launch_bounds__(256)
ln_kernel(const float* __restrict__ x, const float* __restrict__ g,
          const float* __restrict__ b, float* __restrict__ y)
{
    int row  = blockIdx.x*8 + (threadIdx.x >> 5);   // 8 warps per block, 1 row each
    int lane = threadIdx.x & 31;
    const float4 v  = reinterpret_cast<const float4*>(x + (size_t)row*HIDDEN)[lane];
    float s = (v.x+v.y)+(v.z+v.w);
    #pragma unroll
    for (int o=16;o;o>>=1) s += __shfl_xor_sync(0xffffffffu, s, o);
    float mu = s * (1.0f/HIDDEN);
    float dx = v.x-mu, dy = v.y-mu, dz = v.z-mu, dw = v.w-mu;
    float s2 = (dx*dx+dy*dy)+(dz*dz+dw*dw);
    #pragma unroll
    for (int o=16;o;o>>=1) s2 += __shfl_xor_sync(0xffffffffu, s2, o);
    float rs = rsqrtf(s2 * (1.0f/HIDDEN) + 1e-5f);
    const float4 gg = reinterpret_cast<const float4*>(g)[lane];
    const float4 bb = reinterpret_cast<const float4*>(b)[lane];
    float4 o4;
    o4.x = dx*rs*gg.x + bb.x;
    o4.y = dy*rs*gg.y + bb.y;
    o4.z = dz*rs*gg.z + bb.z;
    o4.w = dw*rs*gg.w + bb.w;
    reinterpret_cast<float4*>(y + (size_t)row*HIDDEN)[lane] = o4;
}

// ---------------- fused flash attention, 2 blocks per (batch,head), residual add -------
// Query split: block handles [0,129) or [129,257). 160 threads -> 2 CTAs/SM (reg-limited).
// 16-key score tiles, double-buffered K/V staging: one barrier per tile.
#define KTILE 16
#define ATT_THREADS 160
#define QSPLIT0 129
#define ATT_NT   ((SEQ + KTILE - 1) / KTILE)   // 17 tiles
__global__ void __launch_bounds__(ATT_THREADS)
attention_kernel(const float* __restrict__ qkv, float* __restrict__ out)
{
    __shared__ __align__(16) float Ks[2][KTILE*DHEAD];
    __shared__ __align__(16) float Vs[2][KTILE*DHEAD];
    int bhq = blockIdx.x;                 // (b,h,half)
    int half = bhq & 1;
    int bh   = bhq >> 1;
    int b  = bh >> 1, h = bh & 1;
    int tid = threadIdx.x;
    int r    = (half ? QSPLIT0 : 0) + tid;
    int rend = (half ? SEQ : QSPLIT0);
    bool act = (r < rend);
    const float scale = 0.125f;          // 1/sqrt(64)

    // per-thread staging element indices (tile has KTILE*16 = 256 float4 slots)
    int i0 = tid, i1 = tid + ATT_THREADS;           // i1 valid only when tid < 96
    int j0e = i0 >> 4, e0 = i0 & 15;
    int j1e = i1 >> 4, e1 = i1 & 15;
    const float4* qkv4 = reinterpret_cast<const float4*>(qkv);
    size_t bbase = (size_t)b*SEQ;

    float q[DHEAD], acc[DHEAD];
    float m = -1e30f, l = 0.f;
    if (act) {
        const float4* qrow = qkv4 + (bbase + r)*(3*HIDDEN/4) + h*(DHEAD/4);
        #pragma unroll
        for (int e4=0;e4<DHEAD/4;e4++){
            float4 t = qrow[e4];
            q[e4*4+0]=t.x*scale; q[e4*4+1]=t.y*scale; q[e4*4+2]=t.z*scale; q[e4*4+3]=t.w*scale;
        }
        #pragma unroll
        for (int e=0;e<DHEAD;e++) acc[e]=0.f;
    }

    // preload tile 0 (full KTILE rows; tile 0 always full since SEQ>KTILE)
    {
        size_t rb0 = (bbase + j0e)*(3*HIDDEN/4) + h*(DHEAD/4);
        reinterpret_cast<float4*>(Ks[0])[i0] = qkv4[rb0 + (HIDDEN/4)   + e0];
        reinterpret_cast<float4*>(Vs[0])[i0] = qkv4[rb0 + (2*HIDDEN/4) + e0];
        if (i1 < KTILE*16) {
            size_t rb1 = (bbase + j1e)*(3*HIDDEN/4) + h*(DHEAD/4);
            reinterpret_cast<float4*>(Ks[0])[i1] = qkv4[rb1 + (HIDDEN/4)   + e1];
            reinterpret_cast<float4*>(Vs[0])[i1] = qkv4[rb1 + (2*HIDDEN/4) + e1];
        }
    }
    __syncthreads();

    int buf = 0;
    for (int t = 0; t < ATT_NT; t++) {
        int j0 = t*KTILE;
        int jn = SEQ - j0; if (jn > KTILE) jn = KTILE;
        bool more = (t+1 < ATT_NT);
        // prefetch next tile into registers
        float4 pk0, pv0, pk1, pv1;
        int jnn = 0;
        bool v0f = false, v1f = false;
        if (more) {
            int nj0 = j0 + KTILE;
            jnn = SEQ - nj0; if (jnn > KTILE) jnn = KTILE;
            int lim = jnn*16;
            v0f = (i0 < lim);
            v1f = (i1 < lim);
            if (v0f) {
                size_t rb = (bbase + nj0 + j0e)*(3*HIDDEN/4) + h*(DHEAD/4);
                pk0 = qkv4[rb + (HIDDEN/4)   + e0];
                pv0 = qkv4[rb + (2*HIDDEN/4) + e0];
            }
            if (v1f) {
                size_t rb = (bbase + nj0 + j1e)*(3*HIDDEN/4) + h*(DHEAD/4);
                pk1 = qkv4[rb + (HIDDEN/4)   + e1];
                pv1 = qkv4[rb + (2*HIDDEN/4) + e1];
            }
        }
        // compute on current buffer
        if (act) {
            float s[KTILE];
            float tmax = -1e30f;
            for (int j = 0; j < jn; j++) {
                const float4* kj = reinterpret_cast<const float4*>(Ks[buf] + j*DHEAD);
                float s0=0.f, s1=0.f, s2=0.f, s3=0.f;
                #pragma unroll
                for (int e4=0;e4<DHEAD/4;e4++){
                    float4 kv = kj[e4];
                    s0 += q[e4*4+0]*kv.x;
                    s1 += q[e4*4+1]*kv.y;
                    s2 += q[e4*4+2]*kv.z;
                    s3 += q[e4*4+3]*kv.w;
                }
                s[j] = (s0+s1)+(s2+s3);
                tmax = fmaxf(tmax, s[j]);
            }
            float mnew = fmaxf(m, tmax);
            float corr = expf(m - mnew);
            l *= corr;
            #pragma unroll
            for (int e=0;e<DHEAD;e++) acc[e] *= corr;
            m = mnew;
            for (int j = 0; j < jn; j++) {
                float p = expf(s[j] - mnew);
                l += p;
                const float4* vj = reinterpret_cast<const float4*>(Vs[buf] + j*DHEAD);
                #pragma unroll
                for (int e4=0;e4<DHEAD/4;e4++){
                    float4 vv = vj[e4];
                    acc[e4*4+0] += p*vv.x;
                    acc[e4*4+1] += p*vv.y;
                    acc[e4*4+2] += p*vv.z;
                    acc[e4*4+3] += p*vv.w;
                }
            }
        }
        // store prefetched tile, single barrier per iteration
        if (more) {
            int nb = buf ^ 1;
            if (v0f) {
                reinterpret_cast<float4*>(Ks[nb])[i0] = pk0;
                reinterpret_cast<float4*>(Vs[nb])[i0] = pv0;
            }
            if (v1f) {
                reinterpret_cast<float4*>(Ks[nb])[i1] = pk1;
                reinterpret_cast<float4*>(Vs[nb])[i1] = pv1;
            }
            __syncthreads();
            buf = nb;
        }
    }
    if (act) {
        float inv = 1.0f / l;
        float* orow = out + ((size_t)(bbase + r))*HIDDEN + h*DHEAD;
        #pragma unroll
        for (int e=0;e<DHEAD;e++) orow[e] += acc[e]*inv;
    }
}

// ---------------- classifier head + softmax, one block per batch element ----------------
__global__ void __launch_bounds__(256)
head_kernel(const float* __restrict__ headb, float* __restrict__ dst)
{
    __shared__ float xs[HIDDEN];
    __shared__ float logits[OUTD];
    __shared__ float red[8];
    __shared__ float sval;
    int b = blockIdx.x, tid = threadIdx.x;
    if (tid < HIDDEN) xs[tid] = g_out[(size_t)b*SEQ*HIDDEN + tid];
    __syncthreads();
    for (int n = tid; n < OUTD; n += 256) {
        float s = headb[n];
        #pragma unroll 8
        for (int k = 0; k < HIDDEN; k++) s += xs[k]*g_headWT[(size_t)k*OUTD + n];
        logits[n] = s;
    }
    __syncthreads();
    // max
    float mv = -1e30f;
    for (int n = tid; n < OUTD; n += 256) mv = fmaxf(mv, logits[n]);
    #pragma unroll
    for (int o=16;o;o>>=1) mv = fmaxf(mv, __shfl_xor_sync(0xffffffffu, mv, o));
    if ((tid & 31) == 0) red[tid>>5] = mv;
    __syncthreads();
    if (tid == 0) {
        float t = red[0];
        #pragma unroll
        for (int i=1;i<8;i++) t = fmaxf(t, red[i]);
        sval = t;
    }
    __syncthreads();
    float mx = sval;
    float sum = 0.f;
    for (int n = tid; n < OUTD; n += 256) {
        float e = expf(logits[n] - mx);
        logits[n] = e;
        sum += e;
    }
    #pragma unroll
    for (int o=16;o;o>>=1) sum += __shfl_xor_sync(0xffffffffu, sum, o);
    if ((tid & 31) == 0) red[tid>>5] = sum;
    __syncthreads();
    if (tid == 0) {
        float t = 0.f;
        #pragma unroll
        for (int i=0;i<8;i++) t += red[i];
        sval = t;
    }
    __syncthreads();
    float inv = 1.0f / sval;
    for (int n = tid; n < OUTD; n += 256)
        dst[(size_t)b*OUTD + n] = logits[n]*inv;
}

// ---------------- launch ----------------
extern "C" void kernel_launch(void* const* d_in, const int* in_sizes, int n_in,
                              void* d_out, int out_size)
{
    const float* images = (const float*)d_in[0];
    const float* mapW   = (const float*)d_in[1];
    const float* mapb   = (const float*)d_in[2];
    const float* cls    = (const float*)d_in[3];
    const float* qW     = (const float*)d_in[4];
    const float* qb     = (const float*)d_in[5];
    const float* kW     = (const float*)d_in[6];
    const float* kb     = (const float*)d_in[7];
    const float* vW     = (const float*)d_in[8];
    const float* vb     = (const float*)d_in[9];
    const float* ln1g   = (const float*)d_in[10];
    const float* ln1b   = (const float*)d_in[11];
    const float* ln2g   = (const float*)d_in[12];
    const float* ln2b   = (const float*)d_in[13];
    const float* w1     = (const float*)d_in[14];
    const float* b1     = (const float*)d_in[15];
    const float* w2     = (const float*)d_in[16];
    const float* b2     = (const float*)d_in[17];
    const float* headW  = (const float*)d_in[18];
    const float* headb  = (const float*)d_in[19];
    float* dst = (float*)d_out;

    float *p_out, *p_x, *p_qkv, *p_h1, *p_qkvW, *p_qkvB, *p_w1T, *p_w2T;
    cudaGetSymbolAddress((void**)&p_out,  g_out);
    cudaGetSymbolAddress((void**)&p_x,    g_x);
    cudaGetSymbolAddress((void**)&p_qkv,  g_qkv);
    cudaGetSymbolAddress((void**)&p_h1,   g_h1);
    cudaGetSymbolAddress((void**)&p_qkvW, g_qkvW);
    cudaGetSymbolAddress((void**)&p_qkvB, g_qkvB);
    cudaGetSymbolAddress((void**)&p_w1T,  g_w1T);
    cudaGetSymbolAddress((void**)&p_w2T,  g_w2T);

    // weight prep (cheap, deterministic, runs inside graph)
    prep_kernel<<<(PREP_TOTAL+255)/256, 256>>>(mapW, qW, qb, kW, kb, vW, vb, w1, w2, headW);

    // tokens: cls row + patch embed (+pos)
    cls_pos_kernel<<<(BATCH*HIDDEN+255)/256, 256>>>(cls);
    patch_embed_kernel<<<dim3(HIDDEN/64, MPATCH/64), 256>>>(images, mapb);

    for (int blk = 0; blk < NBLOCKS; blk++) {
        // LN1 -> x  (8 rows per 256-thread block)
        ln_kernel<<<MTOK/8, 256>>>(p_out, ln1g + blk*HIDDEN, ln1b + blk*HIDDEN, p_x);
        // fused qkv projection: (MTOK,128) x (128,384)
        sgemm128_kernel<<<dim3(3*HIDDEN/128, MTOK/128), 256>>>(
            p_x, p_qkvW + (size_t)blk*HIDDEN*3*HIDDEN, p_qkvB + blk*3*HIDDEN,
            p_qkv, 3*HIDDEN, HIDDEN, 0);
        // flash attention with residual add into out (query-split, 2 blocks per bh)
        attention_kernel<<<BATCH*NHEADS*2, ATT_THREADS>>>(p_qkv, p_out);
        // LN2 -> x
        ln_kernel<<<MTOK/8, 256>>>(p_out, ln2g + blk*HIDDEN, ln2b + blk*HIDDEN, p_x);
        // MLP up + gelu
        sgemm128_kernel<<<dim3(MLP/128, MTOK/128), 256>>>(
            p_x, p_w1T + (size_t)blk*HIDDEN*MLP, b1 + blk*MLP,
            p_h1, MLP, HIDDEN, GF_GELU);
        // MLP down, accumulate into residual
        sgemm128_kernel<<<dim3(HIDDEN/128, MTOK/128), 256>>>(
            p_h1, p_w2T + (size_t)blk*MLP*HIDDEN, b2 + blk*HIDDEN,
            p_out, HIDDEN, MLP, GF_ACC);
    }

    // classifier head + softmax
    head_kernel<<<BATCH, 256>>>(headb, dst);
    (void)in_sizes; (void)n_in; (void)out_size;
}